// round 8
// baseline (speedup 1.0000x reference)
#include <cuda_runtime.h>
#include <math.h>

// Shapes (fixed by the problem)
#define BB  2
#define NN  512
#define HID 128
#define DD  32     // Chebyshev orders; decay r~0.70/order -> truncation ~1e-5

// fused-grid layout
#define PRO_BLOCKS 16              // prologue blocks (2 nodes each)
#define PRO_NODES  2
#define MAIN_BLOCKS ((BB * NN) / 2)  // 512 (2 rows per block)
#define TOTAL_BLOCKS (PRO_BLOCKS + MAIN_BLOCKS)

// Scratch (static device globals; no allocation)
__device__ float g_inv_hd;           // 2 / dmax
__device__ float g_G[DD * HID];      // network(+Wo) at Chebyshev nodes
__device__ float g_C[DD * HID];      // Chebyshev coefficients
__device__ unsigned g_flag_dmax;     // 0 -> 1 when g_inv_hd ready
__device__ unsigned g_arrive;        // prologue-internal barrier
__device__ unsigned g_done;          // prologue blocks finished (g_C ready when == PRO_BLOCKS)
__device__ unsigned g_fin;           // main blocks finished; last one resets everything

union SmemU {
    struct {
        float red[128];
        float buf[2][PRO_NODES][HID];   // ping-pong activations
        float costab[PRO_NODES][DD];
        float sG[DD][HID];              // staged G for DCT (16KB)
    } pro;
    struct {
        float sx[NN * 2];
        float sred[4][DD];
    } mn;
};

__global__ __launch_bounds__(128, 6) void fused_kernel(
    const float* __restrict__ x,
    const float* __restrict__ W10, const float* __restrict__ b10,
    const float* __restrict__ W20, const float* __restrict__ b20,
    const float* __restrict__ W11, const float* __restrict__ b11,
    const float* __restrict__ W21, const float* __restrict__ b21,
    const float* __restrict__ W12, const float* __restrict__ b12,
    const float* __restrict__ W22, const float* __restrict__ b22,
    const float* __restrict__ Wo,  const float* __restrict__ bo,
    float* __restrict__ out)
{
    __shared__ SmemU sm;
    const int tid = threadIdx.x;

    if (blockIdx.x < PRO_BLOCKS) {
        // ================= PROLOGUE PATH =================
        const int c  = tid;                       // 0..127
        const int n0 = blockIdx.x * PRO_NODES;    // first node of this block

        // dmax = 2*max||x|| (triangle-inequality bound), deterministic
        float mx = 0.0f;
        for (int t = tid; t < BB * NN; t += 128) {
            float a = x[2 * t], b = x[2 * t + 1];
            mx = fmaxf(mx, fmaf(a, a, b * b));
        }
        sm.pro.red[tid] = mx;
        __syncthreads();
        #pragma unroll
        for (int s = 64; s > 0; s >>= 1) {
            if (tid < s) sm.pro.red[tid] = fmaxf(sm.pro.red[tid], sm.pro.red[tid + s]);
            __syncthreads();
        }
        const float dmax = 2.0f * sqrtf(sm.pro.red[0]) * 1.000001f + 1e-6f;
        if (blockIdx.x == 0 && tid == 0) {
            g_inv_hd = 2.0f / dmax;
            __threadfence();
            atomicExch(&g_flag_dmax, 1u);   // release: main blocks may read inv_hd
        }

        // layer 0 (scalar input): both nodes
        #pragma unroll
        for (int n = 0; n < PRO_NODES; n++) {
            float d = 0.5f * (cospif((n0 + n + 0.5f) * (1.0f / DD)) + 1.0f) * dmax;
            float a = fmaf(d, W10[c], b10[c]);
            sm.pro.buf[0][n][c] = a / (1.0f + expf(-a));
        }
        __syncthreads();

        const float* Ws[6] = {W20, W11, W21, W12, W22, Wo};
        const float* bs[6] = {b20, b11, b21, b12, b22, (const float*)0};
        int cur = 0;
        #pragma unroll
        for (int l = 0; l < 6; l++) {
            const float* __restrict__ W = Ws[l];
            float h0 = 0.0f, h1 = 0.0f;
            #pragma unroll 16
            for (int k = 0; k < HID; k++) {
                const float w = W[k * HID + c];
                h0 = fmaf(sm.pro.buf[cur][0][k], w, h0);
                h1 = fmaf(sm.pro.buf[cur][1][k], w, h1);
            }
            float bbv = bs[l] ? bs[l][c] : 0.0f;
            h0 += bbv; h1 += bbv;
            if (l == 1 || l == 3) {                 // silu after W1_1, W1_2
                h0 = h0 / (1.0f + expf(-h0));
                h1 = h1 / (1.0f + expf(-h1));
            }
            __syncthreads();                        // buf reads done before overwrite
            if (l < 5) {
                sm.pro.buf[cur ^ 1][0][c] = h0;
                sm.pro.buf[cur ^ 1][1][c] = h1;
                cur ^= 1;
                __syncthreads();
            } else {
                g_G[(n0 + 0) * HID + c] = h0;
                g_G[(n0 + 1) * HID + c] = h1;
            }
        }

        // barrier across the 16 prologue blocks (G complete)
        __threadfence();
        __syncthreads();
        if (tid == 0) {
            atomicAdd(&g_arrive, 1u);
            while (*(volatile unsigned*)&g_arrive < (unsigned)PRO_BLOCKS) __nanosleep(32);
        }
        __syncthreads();
        __threadfence();

        // DCT phase: this block produces coefficient rows k = n0, n0+1
        if (tid < PRO_NODES * DD) {
            int qq = tid / DD, m = tid - qq * DD;
            int k = n0 + qq;
            int num = (k * (2 * m + 1)) & (4 * DD - 1);   // cospi period 2 -> mod 128
            sm.pro.costab[qq][m] = cospif((float)num * (1.0f / (2.0f * DD)));
        }
        for (int t = tid; t < DD * HID / 4; t += 128)
            reinterpret_cast<float4*>(sm.pro.sG)[t] =
                __ldcg(reinterpret_cast<const float4*>(g_G) + t);
        __syncthreads();

        #pragma unroll
        for (int qq = 0; qq < PRO_NODES; qq++) {
            int k = n0 + qq;
            float acc = 0.0f;
            #pragma unroll
            for (int m = 0; m < DD; m++) acc = fmaf(sm.pro.costab[qq][m], sm.pro.sG[m][c], acc);
            float wgt = (k == 0) ? (1.0f / DD) : (2.0f / DD);
            g_C[k * HID + c] = acc * wgt;
        }
        __threadfence();
        __syncthreads();
        if (tid == 0) atomicAdd(&g_done, 1u);    // release coefficients
        return;
    }

    // ================= MAIN PATH =================
    const int mb = blockIdx.x - PRO_BLOCKS;      // 0..511
    const int b  = mb >> 8;                      // 256 blocks per batch

    for (int t = tid; t < NN * 2; t += 128) sm.mn.sx[t] = x[b * NN * 2 + t];

    if (tid == 0) {                              // wait for g_inv_hd
        while (*(volatile unsigned*)&g_flag_dmax == 0u) __nanosleep(32);
    }
    __syncthreads();
    __threadfence();
    const float inv_hd = *(volatile float*)&g_inv_hd;

    const int w    = tid >> 5;                   // warp 0..3
    const int lane = tid & 31;
    const int r    = w >> 1;                     // row-in-block 0..1
    const int h    = w & 1;                      // j-half 0..1
    const int i    = ((mb & 255) << 1) + r;      // row within batch
    const float xi0 = sm.mn.sx[2 * i], xi1 = sm.mn.sx[2 * i + 1];

    float s[DD];
    #pragma unroll
    for (int k = 0; k < DD; k++) s[k] = 0.0f;

    #pragma unroll 1
    for (int jj = 0; jj < 2; jj++) {
        const int j0 = h * 256 + jj * 128;
        const int ja = j0 + lane, jb = ja + 32, jc = ja + 64, jd = ja + 96;
        float dxa = xi0 - sm.mn.sx[2 * ja], dya = xi1 - sm.mn.sx[2 * ja + 1];
        float dxb = xi0 - sm.mn.sx[2 * jb], dyb = xi1 - sm.mn.sx[2 * jb + 1];
        float dxc = xi0 - sm.mn.sx[2 * jc], dyc = xi1 - sm.mn.sx[2 * jc + 1];
        float dxd = xi0 - sm.mn.sx[2 * jd], dyd = xi1 - sm.mn.sx[2 * jd + 1];
        float za = fmaf(sqrtf(fmaf(dxa, dxa, dya * dya)), inv_hd, -1.0f);
        float zb = fmaf(sqrtf(fmaf(dxb, dxb, dyb * dyb)), inv_hd, -1.0f);
        float zc = fmaf(sqrtf(fmaf(dxc, dxc, dyc * dyc)), inv_hd, -1.0f);
        float zd = fmaf(sqrtf(fmaf(dxd, dxd, dyd * dyd)), inv_hd, -1.0f);
        za = fminf(fmaxf(za, -1.0f), 1.0f);
        zb = fminf(fmaxf(zb, -1.0f), 1.0f);
        zc = fminf(fmaxf(zc, -1.0f), 1.0f);
        zd = fminf(fmaxf(zd, -1.0f), 1.0f);

        s[1] += (za + zb) + (zc + zd);
        float t0a = 1.0f, t1a = za, z2a = za + za;
        float t0b = 1.0f, t1b = zb, z2b = zb + zb;
        float t0c = 1.0f, t1c = zc, z2c = zc + zc;
        float t0d = 1.0f, t1d = zd, z2d = zd + zd;
        #pragma unroll
        for (int k = 2; k < DD; k++) {
            float ta = fmaf(z2a, t1a, -t0a); t0a = t1a; t1a = ta;
            float tb = fmaf(z2b, t1b, -t0b); t0b = t1b; t1b = tb;
            float tc = fmaf(z2c, t1c, -t0c); t0c = t1c; t1c = tc;
            float td = fmaf(z2d, t1d, -t0d); t0d = t1d; t1d = td;
            s[k] += (ta + tb) + (tc + td);
        }
    }
    // T_0 == 1: each lane processed 2*4 = 8 source nodes
    s[0] = 8.0f;

    // reduce-scatter butterfly over 32 elements: lane ends holding k = lane
    int len = DD / 2;
    #pragma unroll
    for (int off = 16; off > 0; off >>= 1) {
        const bool hi = (lane & off) != 0;
        #pragma unroll
        for (int k = 0; k < 16; k++) {
            if (k >= len) break;
            float send = hi ? s[k] : s[k + len];
            float recv = __shfl_xor_sync(0xffffffffu, send, off);
            s[k] = (hi ? s[k + len] : s[k]) + recv;
        }
        len >>= 1;
    }
    sm.mn.sred[w][lane] = s[0];

    // wait for coefficients (prologue ran concurrently; usually ready by now)
    if (tid == 0) {
        while (*(volatile unsigned*)&g_done < (unsigned)PRO_BLOCKS) __nanosleep(32);
    }
    __syncthreads();       // orders sred stores AND the g_done acquire
    __threadfence();

    // combine the row's two j-halves, contract with C (warp owns 64 columns)
    const float sc = 1.0f / (float)NN;
    const int c0 = h * 64 + lane * 2;
    float accx = bo[c0], accy = bo[c0 + 1];
    #pragma unroll
    for (int k = 0; k < DD; k++) {
        float sk = (sm.mn.sred[2 * r][k] + sm.mn.sred[2 * r + 1][k]) * sc;
        float2 wv = __ldcg(reinterpret_cast<const float2*>(&g_C[k * HID + c0]));
        accx = fmaf(sk, wv.x, accx);
        accy = fmaf(sk, wv.y, accy);
    }
    const int gi = b * NN + i;
    *reinterpret_cast<float2*>(&out[gi * HID + c0]) = make_float2(accx, accy);

    // replay-safe reset: last main block to finish restores all counters to 0
    __threadfence();
    __syncthreads();
    if (tid == 0) {
        unsigned old = atomicAdd(&g_fin, 1u);
        if (old == (unsigned)(MAIN_BLOCKS - 1)) {
            g_flag_dmax = 0u;
            g_arrive    = 0u;
            g_done      = 0u;
            g_fin       = 0u;
            __threadfence();
        }
    }
}

// ---------------------------------------------------------------------------
// Launch: ONE graph-capturable kernel (prologue and main phases overlap via
// device-side flags; all counters restored to 0 before exit every launch).
// Input order: x, W1_0,b1_0,W2_0,b2_0, W1_1,b1_1,W2_1,b2_1, W1_2,b1_2,W2_2,b2_2, Wo,bo
// ---------------------------------------------------------------------------
extern "C" void kernel_launch(void* const* d_in, const int* in_sizes, int n_in,
                              void* d_out, int out_size)
{
    const float* x   = (const float*)d_in[0];
    const float* W10 = (const float*)d_in[1];
    const float* b10 = (const float*)d_in[2];
    const float* W20 = (const float*)d_in[3];
    const float* b20 = (const float*)d_in[4];
    const float* W11 = (const float*)d_in[5];
    const float* b11 = (const float*)d_in[6];
    const float* W21 = (const float*)d_in[7];
    const float* b21 = (const float*)d_in[8];
    const float* W12 = (const float*)d_in[9];
    const float* b12 = (const float*)d_in[10];
    const float* W22 = (const float*)d_in[11];
    const float* b22 = (const float*)d_in[12];
    const float* Wo  = (const float*)d_in[13];
    const float* bo  = (const float*)d_in[14];
    float* out = (float*)d_out;

    fused_kernel<<<TOTAL_BLOCKS, 128>>>(x, W10, b10, W20, b20, W11, b11,
                                        W21, b21, W12, b12, W22, b22, Wo, bo, out);
}

// round 9
// speedup vs baseline: 1.3494x; 1.3494x over previous
#include <cuda_runtime.h>
#include <math.h>

// Shapes (fixed by the problem)
#define BB  2
#define NN  512
#define HID 128
#define DD  32    // Chebyshev orders; measured: truncation below fp32 noise at 32

// fused prologue tiling
#define NODES 4                    // Chebyshev nodes per block
#define KSPL  4                    // k-dimension split
#define NE_BLOCKS (DD / NODES)     // 8
#define NE_THREADS (HID * KSPL)    // 512

// Scratch (static device globals; no allocation)
__device__ float g_inv_hd;        // 2 / dmax
__device__ float g_G[DD * HID];   // network(+Wo) at Chebyshev nodes
__device__ float g_C[DD * HID];   // Chebyshev coefficients
__device__ unsigned g_arrive;     // grid barrier counter (0 at start AND end of every launch)

// ---------------------------------------------------------------------------
// Fused prologue: phase 1 = exact fp32 network at DD Chebyshev nodes (+Wo fold),
// phase 2 (after 8-block grid barrier) = DCT-II -> coefficients.
// 8 blocks x 512 threads; thread (q,c): q = k-quarter / node slot, c = column.
// Weight prefetch double-buffers the next layer's 32 LDGs under current compute.
// ---------------------------------------------------------------------------
__global__ __launch_bounds__(NE_THREADS) void prologue_kernel(
    const float* __restrict__ x,
    const float* __restrict__ W10, const float* __restrict__ b10,
    const float* __restrict__ W20, const float* __restrict__ b20,
    const float* __restrict__ W11, const float* __restrict__ b11,
    const float* __restrict__ W21, const float* __restrict__ b21,
    const float* __restrict__ W12, const float* __restrict__ b12,
    const float* __restrict__ W22, const float* __restrict__ b22,
    const float* __restrict__ Wo)
{
    __shared__ float red[NE_THREADS];
    __shared__ float buf[NODES][HID];          // current activations
    __shared__ float part[KSPL][NODES][HID];   // per-quarter partials
    __shared__ float costab[NODES][DD];        // phase 2: cos table (4 k x 32 m)
    __shared__ float sG[DD][HID];              // phase 2: staged G (16KB)

    const int c = threadIdx.x & (HID - 1);
    const int q = threadIdx.x >> 7;            // 0..3
    const int k0 = q * (HID / KSPL);           // 32 k's per quarter

    const float* Ws[6] = {W20, W11, W21, W12, W22, Wo};
    const float* bs[6] = {b20, b11, b21, b12, b22, (const float*)0};

    // issue layer-0 weight loads early (independent of everything below)
    float wc[HID / KSPL];
    #pragma unroll
    for (int kk = 0; kk < HID / KSPL; kk++) wc[kk] = Ws[0][(k0 + kk) * HID + c];

    // dmax = 2*max||x|| (triangle-inequality bound), deterministic per block
    float mx = 0.0f;
    for (int t = threadIdx.x; t < BB * NN; t += NE_THREADS) {
        float a = x[2 * t], b = x[2 * t + 1];
        mx = fmaxf(mx, fmaf(a, a, b * b));
    }
    red[threadIdx.x] = mx;
    __syncthreads();
    #pragma unroll
    for (int s = NE_THREADS / 2; s > 0; s >>= 1) {
        if (threadIdx.x < s) red[threadIdx.x] = fmaxf(red[threadIdx.x], red[threadIdx.x + s]);
        __syncthreads();
    }
    const float dmax = 2.0f * sqrtf(red[0]) * 1.000001f + 1e-6f;
    if (blockIdx.x == 0 && threadIdx.x == 0) g_inv_hd = 2.0f / dmax;

    // layer 0 (scalar input): thread-set q computes node q of this block
    {
        int mnode = blockIdx.x * NODES + q;
        float d = 0.5f * (cospif((mnode + 0.5f) * (1.0f / DD)) + 1.0f) * dmax;
        float a = fmaf(d, W10[c], b10[c]);
        buf[q][c] = a / (1.0f + expf(-a));
    }
    __syncthreads();

    #pragma unroll
    for (int l = 0; l < 6; l++) {
        // prefetch next layer's weights (hides LDG latency under compute+syncs)
        float wn[HID / KSPL];
        if (l < 5) {
            #pragma unroll
            for (int kk = 0; kk < HID / KSPL; kk++)
                wn[kk] = Ws[l + 1][(k0 + kk) * HID + c];
        }
        float h0 = 0.0f, h1 = 0.0f, h2 = 0.0f, h3 = 0.0f;
        #pragma unroll
        for (int kk = 0; kk < HID / KSPL; kk++) {
            const int k = k0 + kk;
            const float w = wc[kk];
            h0 = fmaf(buf[0][k], w, h0);
            h1 = fmaf(buf[1][k], w, h1);
            h2 = fmaf(buf[2][k], w, h2);
            h3 = fmaf(buf[3][k], w, h3);
        }
        part[q][0][c] = h0;
        part[q][1][c] = h1;
        part[q][2][c] = h2;
        part[q][3][c] = h3;
        __syncthreads();
        float v = (bs[l] ? bs[l][c] : 0.0f) +
                  ((part[0][q][c] + part[1][q][c]) + (part[2][q][c] + part[3][q][c]));
        if (l == 1 || l == 3) v = v / (1.0f + expf(-v));   // silu after W1_1, W1_2
        if (l < 5) buf[q][c] = v;                          // reads of buf done pre-sync
        else g_G[(blockIdx.x * NODES + q) * HID + c] = v;
        __syncthreads();
        #pragma unroll
        for (int kk = 0; kk < HID / KSPL; kk++) wc[kk] = wn[kk];
    }

    // ---- grid barrier across the 8 co-resident blocks (replay-safe) ----
    __threadfence();
    if (threadIdx.x == 0) {
        atomicAdd(&g_arrive, 1u);
        while (*(volatile unsigned*)&g_arrive < (unsigned)NE_BLOCKS) __nanosleep(32);
    }
    __syncthreads();
    __threadfence();

    // ---- phase 2: DCT-II. Block handles k = blockIdx*4 + q. ----
    // cos table: 4*32 = 128 distinct angles per block
    for (int t = threadIdx.x; t < NODES * DD; t += NE_THREADS) {
        int qq = t / DD, m = t - qq * DD;
        int k = blockIdx.x * NODES + qq;
        int num = (k * (2 * m + 1)) & (4 * DD - 1);   // cospi period 2 -> mod 128
        costab[qq][m] = cospif((float)num * (1.0f / (2.0f * DD)));
    }
    // stage G in smem (vectorized, L1-bypassing: cross-block data)
    for (int t = threadIdx.x; t < DD * HID / 4; t += NE_THREADS)
        reinterpret_cast<float4*>(sG)[t] =
            __ldcg(reinterpret_cast<const float4*>(g_G) + t);
    __syncthreads();

    {
        int k = blockIdx.x * NODES + q;
        float acc = 0.0f;
        #pragma unroll
        for (int m = 0; m < DD; m++) acc = fmaf(costab[q][m], sG[m][c], acc);
        float wgt = (k == 0) ? (1.0f / DD) : (2.0f / DD);
        g_C[k * HID + c] = acc * wgt;
    }

    // exit: restore barrier counter to 0 for the next graph replay
    __syncthreads();
    if (threadIdx.x == 0) atomicSub(&g_arrive, 1u);
}

// ---------------------------------------------------------------------------
// Hot kernel: per (b,i), s[k] = sum_j T_k(z_ij); out = (1/N) s@C + bo.
// 512 blocks x 128 thr: block = 2 rows, each row = 2 warps (j-split 256 each).
// 4 independent recurrence chains per lane hide FMA lat-4.
// Butterfly (5 stages, 31 shfl): lane ends holding fully-reduced k = lane.
// ---------------------------------------------------------------------------
__global__ __launch_bounds__(128, 8) void cheb_main_kernel(
    const float* __restrict__ x, const float* __restrict__ bo,
    float* __restrict__ out)
{
    __shared__ float sx[NN * 2];
    __shared__ float sred[4][DD];          // per-warp reduced s

    const float inv_hd = g_inv_hd;         // published by prologue

    const int b = blockIdx.x >> 8;         // 256 blocks per batch
    for (int t = threadIdx.x; t < NN * 2; t += 128) sx[t] = x[b * NN * 2 + t];
    __syncthreads();

    const int w    = threadIdx.x >> 5;     // warp 0..3
    const int lane = threadIdx.x & 31;
    const int r    = w >> 1;               // row-in-block 0..1
    const int h    = w & 1;                // j-half 0..1
    const int i    = ((blockIdx.x & 255) << 1) + r;   // row within batch
    const float xi0 = sx[2 * i], xi1 = sx[2 * i + 1];

    float s[DD];
    #pragma unroll
    for (int k = 0; k < DD; k++) s[k] = 0.0f;

    #pragma unroll 1
    for (int jj = 0; jj < 2; jj++) {
        const int j0 = h * 256 + jj * 128;
        const int ja = j0 + lane, jb = ja + 32, jc = ja + 64, jd = ja + 96;
        float dxa = xi0 - sx[2 * ja], dya = xi1 - sx[2 * ja + 1];
        float dxb = xi0 - sx[2 * jb], dyb = xi1 - sx[2 * jb + 1];
        float dxc = xi0 - sx[2 * jc], dyc = xi1 - sx[2 * jc + 1];
        float dxd = xi0 - sx[2 * jd], dyd = xi1 - sx[2 * jd + 1];
        float za = fmaf(sqrtf(fmaf(dxa, dxa, dya * dya)), inv_hd, -1.0f);
        float zb = fmaf(sqrtf(fmaf(dxb, dxb, dyb * dyb)), inv_hd, -1.0f);
        float zc = fmaf(sqrtf(fmaf(dxc, dxc, dyc * dyc)), inv_hd, -1.0f);
        float zd = fmaf(sqrtf(fmaf(dxd, dxd, dyd * dyd)), inv_hd, -1.0f);
        za = fminf(fmaxf(za, -1.0f), 1.0f);
        zb = fminf(fmaxf(zb, -1.0f), 1.0f);
        zc = fminf(fmaxf(zc, -1.0f), 1.0f);
        zd = fminf(fmaxf(zd, -1.0f), 1.0f);

        s[1] += (za + zb) + (zc + zd);
        float t0a = 1.0f, t1a = za, z2a = za + za;
        float t0b = 1.0f, t1b = zb, z2b = zb + zb;
        float t0c = 1.0f, t1c = zc, z2c = zc + zc;
        float t0d = 1.0f, t1d = zd, z2d = zd + zd;
        #pragma unroll
        for (int k = 2; k < DD; k++) {
            float ta = fmaf(z2a, t1a, -t0a); t0a = t1a; t1a = ta;
            float tb = fmaf(z2b, t1b, -t0b); t0b = t1b; t1b = tb;
            float tc = fmaf(z2c, t1c, -t0c); t0c = t1c; t1c = tc;
            float td = fmaf(z2d, t1d, -t0d); t0d = t1d; t1d = td;
            s[k] += (ta + tb) + (tc + td);
        }
    }
    // T_0 == 1: each lane processed 256/32 = 8 source nodes
    s[0] = 8.0f;

    // reduce-scatter butterfly over 32 elements: lane ends holding k = lane
    int len = DD / 2;
    #pragma unroll
    for (int off = 16; off > 0; off >>= 1) {
        const bool hi = (lane & off) != 0;
        #pragma unroll
        for (int k = 0; k < 16; k++) {
            if (k >= len) break;
            float send = hi ? s[k] : s[k + len];
            float recv = __shfl_xor_sync(0xffffffffu, send, off);
            s[k] = (hi ? s[k + len] : s[k]) + recv;
        }
        len >>= 1;
    }
    sred[w][lane] = s[0];
    __syncthreads();

    // combine the row's two j-halves and contract with C.
    // Each warp handles 64 of the row's 128 output columns (float2 per lane).
    const float sc = 1.0f / (float)NN;
    const int c0 = h * 64 + lane * 2;
    float accx = bo[c0], accy = bo[c0 + 1];
    #pragma unroll
    for (int k = 0; k < DD; k++) {
        float sk = (sred[2 * r][k] + sred[2 * r + 1][k]) * sc;
        float2 wv = *reinterpret_cast<const float2*>(&g_C[k * HID + c0]);
        accx = fmaf(sk, wv.x, accx);
        accy = fmaf(sk, wv.y, accy);
    }
    const int gi = b * NN + i;
    *reinterpret_cast<float2*>(&out[gi * HID + c0]) = make_float2(accx, accy);
}

// ---------------------------------------------------------------------------
// Launch: 2 graph-capturable kernels.
// Input order: x, W1_0,b1_0,W2_0,b2_0, W1_1,b1_1,W2_1,b2_1, W1_2,b1_2,W2_2,b2_2, Wo,bo
// ---------------------------------------------------------------------------
extern "C" void kernel_launch(void* const* d_in, const int* in_sizes, int n_in,
                              void* d_out, int out_size)
{
    const float* x   = (const float*)d_in[0];
    const float* W10 = (const float*)d_in[1];
    const float* b10 = (const float*)d_in[2];
    const float* W20 = (const float*)d_in[3];
    const float* b20 = (const float*)d_in[4];
    const float* W11 = (const float*)d_in[5];
    const float* b11 = (const float*)d_in[6];
    const float* W21 = (const float*)d_in[7];
    const float* b21 = (const float*)d_in[8];
    const float* W12 = (const float*)d_in[9];
    const float* b12 = (const float*)d_in[10];
    const float* W22 = (const float*)d_in[11];
    const float* b22 = (const float*)d_in[12];
    const float* Wo  = (const float*)d_in[13];
    const float* bo  = (const float*)d_in[14];
    float* out = (float*)d_out;

    prologue_kernel<<<NE_BLOCKS, NE_THREADS>>>(x, W10, b10, W20, b20, W11, b11,
                                               W21, b21, W12, b12, W22, b22, Wo);
    cheb_main_kernel<<<(BB * NN) / 2, 128>>>(x, bo, out);
}